// round 13
// baseline (speedup 1.0000x reference)
#include <cuda_runtime.h>
#include <math.h>
#include <stdint.h>

#define B_  2
#define S_  2048
#define D_  1024
#define H_  16
#define DK_ 64
#define NEGV  -1000000000.0f

// ---------------- scratch ----------------
// g_Q, g_K: packed per-row layout  [b,h,s, perm8(d)]  perm8(d) = (d&3)*16 + (d>>2)
// g_V: transposed packed           [b,h,d, 64*tile + perm8(s&63)]
__device__ float g_Q[B_*H_*S_*DK_];
__device__ float g_K[B_*H_*S_*DK_];
__device__ float g_V[B_*H_*S_*DK_];
__device__ float g_ctx[B_*S_*D_];     // [b,s,h*d]

__device__ __forceinline__ unsigned f2tf(float x) {
    unsigned r; asm("cvt.rna.tf32.f32 %0, %1;" : "=r"(r) : "f"(x)); return r;
}
__device__ __forceinline__ float f2tff(float x) { return __uint_as_float(f2tf(x)); }
__device__ __forceinline__ unsigned uf(float x) { return __float_as_uint(x); }

__device__ __forceinline__ void mma8(float* c, const unsigned* a, unsigned b0, unsigned b1) {
    asm volatile(
        "mma.sync.aligned.m16n8k8.row.col.f32.tf32.tf32.f32 "
        "{%0,%1,%2,%3}, {%4,%5,%6,%7}, {%8,%9}, {%0,%1,%2,%3};"
        : "+f"(c[0]), "+f"(c[1]), "+f"(c[2]), "+f"(c[3])
        : "r"(a[0]), "r"(a[1]), "r"(a[2]), "r"(a[3]), "r"(b0), "r"(b1));
}

// ---------------- GEMM core (R4 structure — known good) -------------------
// Y[m,n] = (sum_k X[m,k]*W[n,k] + bias[n]) * scale
// CTA 128x128x32, 8 warps (2x4), warp tile 64x32.
// smem per row: 32 k-values permuted pos=(k&3)*8+(k>>2), stride 36.
// modes: 0 plain [M,N]; 1 packed bhsd (Q/K); 2 transposed packed (V).
#define GK 1024
#define GN 1024

__device__ __forceinline__
void gemm_body(const float* __restrict__ X, const float* __restrict__ W,
               const float* __restrict__ bias, float scale,
               float* __restrict__ Y, int mode,
               float* Xs, float* Ws)
{
    const int tid  = threadIdx.x;
    const int lane = tid & 31;
    const int wid  = tid >> 5;
    const int g = lane >> 2, q = lane & 3;
    const int wm = wid >> 2, wn = wid & 3;
    const int m0 = blockIdx.y * 128, n0 = blockIdx.x * 128;

    float c[4][4][4];
#pragma unroll
    for (int i = 0; i < 4; i++)
#pragma unroll
        for (int j = 0; j < 4; j++)
#pragma unroll
            for (int k = 0; k < 4; k++) c[i][j][k] = 0.0f;

    for (int k0 = 0; k0 < GK; k0 += 32) {
#pragma unroll
        for (int i = 0; i < 4; i++) {
            int idx = tid + i * 256;            // 0..1023
            int row = idx >> 3;                 // 0..127
            int kq  = (idx & 7) * 4;            // 0..28
            int base = row * 36 + (kq >> 2);
            float4 xv = *(const float4*)(X + (size_t)(m0 + row) * GK + k0 + kq);
            Xs[base     ] = f2tff(xv.x);
            Xs[base +  8] = f2tff(xv.y);
            Xs[base + 16] = f2tff(xv.z);
            Xs[base + 24] = f2tff(xv.w);
            float4 wv = *(const float4*)(W + (size_t)(n0 + row) * GK + k0 + kq);
            Ws[base     ] = f2tff(wv.x);
            Ws[base +  8] = f2tff(wv.y);
            Ws[base + 16] = f2tff(wv.z);
            Ws[base + 24] = f2tff(wv.w);
        }
        __syncthreads();

#pragma unroll
        for (int p = 0; p < 2; p++) {
            const int cofs = q * 8 + 4 * p;
            unsigned bb[4][4];
#pragma unroll
            for (int jn = 0; jn < 4; jn++) {
                int nb = wn * 32 + jn * 8 + g;
                float4 wr = *(const float4*)(Ws + nb * 36 + cofs);
                bb[jn][0] = uf(wr.x); bb[jn][1] = uf(wr.y);
                bb[jn][2] = uf(wr.z); bb[jn][3] = uf(wr.w);
            }
#pragma unroll
            for (int im = 0; im < 4; im++) {
                int rb = wm * 64 + im * 16;
                float4 ar = *(const float4*)(Xs + (rb + g    ) * 36 + cofs);
                float4 br = *(const float4*)(Xs + (rb + g + 8) * 36 + cofs);
                unsigned aE[4] = { uf(ar.x), uf(br.x), uf(ar.y), uf(br.y) };
                unsigned aO[4] = { uf(ar.z), uf(br.z), uf(ar.w), uf(br.w) };
#pragma unroll
                for (int jn = 0; jn < 4; jn++) {
                    mma8(c[im][jn], aE, bb[jn][0], bb[jn][1]);
                    mma8(c[im][jn], aO, bb[jn][2], bb[jn][3]);
                }
            }
        }
        __syncthreads();
    }

    // epilogue
#pragma unroll
    for (int im = 0; im < 4; im++) {
#pragma unroll
        for (int jn = 0; jn < 4; jn++) {
            int n  = n0 + wn * 32 + jn * 8 + 2 * q;
            int mA = m0 + wm * 64 + im * 16 + g;
            int mB = mA + 8;
            float b0v = bias[n], b1v = bias[n + 1];
            float v0 = (c[im][jn][0] + b0v) * scale;
            float v1 = (c[im][jn][1] + b1v) * scale;
            float v2 = (c[im][jn][2] + b0v) * scale;
            float v3 = (c[im][jn][3] + b1v) * scale;
            if (mode == 0) {
                *(float2*)(Y + (size_t)mA * GN + n) = make_float2(v0, v1);
                *(float2*)(Y + (size_t)mB * GN + n) = make_float2(v2, v3);
            } else if (mode == 1) {
                int h = n >> 6, d0 = n & 63, d1 = d0 + 1;
                int p0 = (d0 & 3) * 16 + (d0 >> 2);
                int p1 = (d1 & 3) * 16 + (d1 >> 2);
                {
                    int b = mA >> 11, s = mA & (S_ - 1);
                    float* base = Y + (size_t)((b*H_ + h)*S_ + s) * 64;
                    base[p0] = f2tff(v0); base[p1] = f2tff(v1);
                }
                {
                    int b = mB >> 11, s = mB & (S_ - 1);
                    float* base = Y + (size_t)((b*H_ + h)*S_ + s) * 64;
                    base[p0] = f2tff(v2); base[p1] = f2tff(v3);
                }
            } else {
                int h = n >> 6, d0 = n & 63, d1 = d0 + 1;
                {
                    int b = mA >> 11, s = mA & (S_ - 1);
                    int ps = (s & ~63) + (s & 3) * 16 + ((s & 63) >> 2);
                    Y[(size_t)((b*H_ + h)*64 + d0) * S_ + ps] = f2tff(v0);
                    Y[(size_t)((b*H_ + h)*64 + d1) * S_ + ps] = f2tff(v1);
                }
                {
                    int b = mB >> 11, s = mB & (S_ - 1);
                    int ps = (s & ~63) + (s & 3) * 16 + ((s & 63) >> 2);
                    Y[(size_t)((b*H_ + h)*64 + d0) * S_ + ps] = f2tff(v2);
                    Y[(size_t)((b*H_ + h)*64 + d1) * S_ + ps] = f2tff(v3);
                }
            }
        }
    }
}

// Fused Q/K/V projection: blockIdx.z selects which projection this CTA does.
__global__ __launch_bounds__(256, 2)
void gemm_qkv(const float* __restrict__ query, const float* __restrict__ key,
              const float* __restrict__ value,
              const float* __restrict__ wq, const float* __restrict__ bq,
              const float* __restrict__ wk, const float* __restrict__ bk,
              const float* __restrict__ wv, const float* __restrict__ bv,
              float* __restrict__ gQ, float* __restrict__ gK, float* __restrict__ gV)
{
    __shared__ float Xs[128 * 36];
    __shared__ float Ws[128 * 36];
    const int z = blockIdx.z;
    if (z == 0)      gemm_body(query, wq, bq, 0.125f, gQ, 1, Xs, Ws);
    else if (z == 1) gemm_body(key,   wk, bk, 1.0f,   gK, 1, Xs, Ws);
    else             gemm_body(value, wv, bv, 1.0f,   gV, 2, Xs, Ws);
}

__global__ __launch_bounds__(256, 2)
void gemm_out(const float* __restrict__ X, const float* __restrict__ W,
              const float* __restrict__ bias, float* __restrict__ Y)
{
    __shared__ float Xs[128 * 36];
    __shared__ float Ws[128 * 36];
    gemm_body(X, W, bias, 1.0f, Y, 0, Xs, Ws);
}

// ---------------- flash attention (conflict-free chunk swizzle) -----------
// grid: (S/64, H, B); block 128 = 4 warps; warp owns 16 q-rows.
// Storage swizzle: chunk c of row r stored at position c ^ ((c&8)>>2) ^ (r&1).
// Read side: lane (g,q) reads logical chunk q*4+kkp -> XOR constant
// xc = (q&2)^(g&1), giving 8 distinct bank-groups per 8-lane phase (was
// degree-2 conflicted with the old (g&1)<<2 swizzle).
__global__ __launch_bounds__(128, 3)
void attn_tf32(const int* __restrict__ mask)
{
    __shared__ float Ks[64 * 64];
    __shared__ float Vs[64 * 64];
    __shared__ int   mks[64];

    const int tid  = threadIdx.x;
    const int lane = tid & 31;
    const int wid  = tid >> 5;
    const int g = lane >> 2, q = lane & 3;
    const int q0 = blockIdx.x * 64;
    const int h  = blockIdx.y;
    const int b  = blockIdx.z;
    const int wb = wid * 16;
    const int bh = b * H_ + h;
    const unsigned xc = (q & 2) ^ (g & 1);   // lane-constant chunk XOR

    // Q fragments direct from packed global (already tf32)
    const float* Qp = g_Q + (size_t)(bh * S_ + q0 + wb) * 64;
    unsigned qa[8][4];
#pragma unroll
    for (int p = 0; p < 4; p++) {
        float4 AR = *(const float4*)(Qp + (g    ) * 64 + (q * 4 + p) * 4);
        float4 BR = *(const float4*)(Qp + (g + 8) * 64 + (q * 4 + p) * 4);
        qa[2*p  ][0] = uf(AR.x); qa[2*p  ][1] = uf(BR.x);
        qa[2*p  ][2] = uf(AR.y); qa[2*p  ][3] = uf(BR.y);
        qa[2*p+1][0] = uf(AR.z); qa[2*p+1][1] = uf(BR.z);
        qa[2*p+1][2] = uf(AR.w); qa[2*p+1][3] = uf(BR.w);
    }
    const bool mr1 = mask[b*S_ + q0 + wb + g    ] != 0;
    const bool mr2 = mask[b*S_ + q0 + wb + g + 8] != 0;

    float m1 = -INFINITY, m2 = -INFINITY, l1 = 0.0f, l2 = 0.0f;
    float o[8][4];
#pragma unroll
    for (int j = 0; j < 8; j++)
#pragma unroll
        for (int k = 0; k < 4; k++) o[j][k] = 0.0f;

    const float4* K4 = (const float4*)(g_K + (size_t)bh * S_ * 64);
    const float*  Vt = g_V + (size_t)bh * 64 * S_;

    const int srcA = (lane & ~3) | (q >> 1);
    const int srcB = srcA + 2;
    const bool hi  = q & 1;

    for (int kt = 0; kt < S_ / 64; kt++) {
        __syncthreads();
#pragma unroll
        for (int t = 0; t < 8; t++) {
            int id  = tid + t * 128;
            int row = id >> 4, c16 = id & 15;
            int ph  = (c16 ^ ((c16 & 8) >> 2) ^ (row & 1)) << 2;
            *(float4*)(Ks + row * 64 + ph) = K4[(size_t)(kt * 64 + row) * 16 + c16];
            *(float4*)(Vs + row * 64 + ph) =
                *(const float4*)(Vt + (size_t)row * S_ + kt * 64 + c16 * 4);
        }
        if (tid < 64) mks[tid] = mask[b*S_ + kt*64 + tid];
        __syncthreads();

        // S = Q @ K^T
        float s[8][4];
#pragma unroll
        for (int j = 0; j < 8; j++) {
            s[j][0] = s[j][1] = s[j][2] = s[j][3] = 0.0f;
            const float* Kr = Ks + (j * 8 + g) * 64;
#pragma unroll
            for (int t = 0; t < 4; t++) {
                int kkp = (t + q) & 3;
                float4 w = *(const float4*)(Kr + (((q * 4 + kkp) ^ xc) << 2));
                mma8(s[j], qa[2*kkp  ], uf(w.x), uf(w.y));
                mma8(s[j], qa[2*kkp+1], uf(w.z), uf(w.w));
            }
        }

        // mask
#pragma unroll
        for (int j = 0; j < 8; j++) {
            int c0 = j * 8 + 2 * q;
            bool k0m = mks[c0] != 0, k1m = mks[c0 + 1] != 0;
            s[j][0] = (mr1 && k0m) ? s[j][0] : NEGV;
            s[j][1] = (mr1 && k1m) ? s[j][1] : NEGV;
            s[j][2] = (mr2 && k0m) ? s[j][2] : NEGV;
            s[j][3] = (mr2 && k1m) ? s[j][3] : NEGV;
        }

        // online softmax
        float t1 = -INFINITY, t2 = -INFINITY;
#pragma unroll
        for (int j = 0; j < 8; j++) {
            t1 = fmaxf(t1, fmaxf(s[j][0], s[j][1]));
            t2 = fmaxf(t2, fmaxf(s[j][2], s[j][3]));
        }
        t1 = fmaxf(t1, __shfl_xor_sync(0xffffffffu, t1, 1));
        t1 = fmaxf(t1, __shfl_xor_sync(0xffffffffu, t1, 2));
        t2 = fmaxf(t2, __shfl_xor_sync(0xffffffffu, t2, 1));
        t2 = fmaxf(t2, __shfl_xor_sync(0xffffffffu, t2, 2));

        float n1 = fmaxf(m1, t1), n2 = fmaxf(m2, t2);
        float a1 = __expf(m1 - n1), a2 = __expf(m2 - n2);
        m1 = n1; m2 = n2;

        float r1 = 0.0f, r2 = 0.0f;
#pragma unroll
        for (int j = 0; j < 8; j++) {
            s[j][0] = __expf(s[j][0] - n1); s[j][1] = __expf(s[j][1] - n1);
            s[j][2] = __expf(s[j][2] - n2); s[j][3] = __expf(s[j][3] - n2);
            r1 += s[j][0] + s[j][1];
            r2 += s[j][2] + s[j][3];
        }
        r1 += __shfl_xor_sync(0xffffffffu, r1, 1);
        r1 += __shfl_xor_sync(0xffffffffu, r1, 2);
        r2 += __shfl_xor_sync(0xffffffffu, r2, 1);
        r2 += __shfl_xor_sync(0xffffffffu, r2, 2);
        l1 = l1 * a1 + r1;
        l2 = l2 * a2 + r2;
#pragma unroll
        for (int j = 0; j < 8; j++) {
            o[j][0] *= a1; o[j][1] *= a1; o[j][2] *= a2; o[j][3] *= a2;
        }

        // P: C-layout -> A-fragment via shuffles
        unsigned pa[8][4];
#pragma unroll
        for (int kk = 0; kk < 8; kk++) {
            float u0 = __shfl_sync(0xffffffffu, s[kk][0], srcA);
            float u1 = __shfl_sync(0xffffffffu, s[kk][1], srcA);
            float u2 = __shfl_sync(0xffffffffu, s[kk][2], srcA);
            float u3 = __shfl_sync(0xffffffffu, s[kk][3], srcA);
            float v0 = __shfl_sync(0xffffffffu, s[kk][0], srcB);
            float v1 = __shfl_sync(0xffffffffu, s[kk][1], srcB);
            float v2 = __shfl_sync(0xffffffffu, s[kk][2], srcB);
            float v3 = __shfl_sync(0xffffffffu, s[kk][3], srcB);
            pa[kk][0] = f2tf(hi ? u1 : u0);
            pa[kk][1] = f2tf(hi ? u3 : u2);
            pa[kk][2] = f2tf(hi ? v1 : v0);
            pa[kk][3] = f2tf(hi ? v3 : v2);
        }

        // O += P @ V
#pragma unroll
        for (int j = 0; j < 8; j++) {
            const float* Vr = Vs + (j * 8 + g) * 64;
#pragma unroll
            for (int t = 0; t < 4; t++) {
                int kkp = (t + q) & 3;
                float4 w = *(const float4*)(Vr + (((q * 4 + kkp) ^ xc) << 2));
                mma8(o[j], pa[2*kkp  ], uf(w.x), uf(w.y));
                mma8(o[j], pa[2*kkp+1], uf(w.z), uf(w.w));
            }
        }
    }

    // epilogue
    float i1 = 1.0f / l1, i2 = 1.0f / l2;
    int r1g = q0 + wb + g, r2g = r1g + 8;
#pragma unroll
    for (int j = 0; j < 8; j++) {
        int col = h * 64 + j * 8 + 2 * q;
        *(float2*)(g_ctx + (size_t)(b*S_ + r1g) * D_ + col) =
            make_float2(o[j][0]*i1, o[j][1]*i1);
        *(float2*)(g_ctx + (size_t)(b*S_ + r2g) * D_ + col) =
            make_float2(o[j][2]*i2, o[j][3]*i2);
    }
}

// ---------------- host ----------------
extern "C" void kernel_launch(void* const* d_in, const int* in_sizes, int n_in,
                              void* d_out, int out_size)
{
    const float* query = (const float*)d_in[0];
    const float* key   = (const float*)d_in[1];
    const float* value = (const float*)d_in[2];
    const int*   mask  = (const int*)  d_in[3];
    const float* wq = (const float*)d_in[4];
    const float* bq = (const float*)d_in[5];
    const float* wk = (const float*)d_in[6];
    const float* bk = (const float*)d_in[7];
    const float* wv = (const float*)d_in[8];
    const float* bv = (const float*)d_in[9];
    const float* wo = (const float*)d_in[10];
    const float* bo = (const float*)d_in[11];

    float *gQ, *gK, *gV, *gctx;
    cudaGetSymbolAddress((void**)&gQ,   g_Q);
    cudaGetSymbolAddress((void**)&gK,   g_K);
    cudaGetSymbolAddress((void**)&gV,   g_V);
    cudaGetSymbolAddress((void**)&gctx, g_ctx);

    dim3 gq(GN / 128, 4096 / 128, 3);   // (8, 32, 3): fused Q/K/V projections
    gemm_qkv<<<gq, 256>>>(query, key, value, wq, bq, wk, bk, wv, bv, gQ, gK, gV);

    attn_tf32<<<dim3(S_/64, H_, B_), 128>>>(mask);

    dim3 go(GN / 128, 4096 / 128);      // (8, 32)
    gemm_out<<<go, 256>>>(gctx, wo, bo, (float*)d_out);
}

// round 15
// speedup vs baseline: 1.1714x; 1.1714x over previous
#include <cuda_runtime.h>
#include <math.h>
#include <stdint.h>

#define B_  2
#define S_  2048
#define D_  1024
#define H_  16
#define DK_ 64
#define NEGV  -1000000000.0f

// ---------------- scratch ----------------
// g_Q, g_K: packed per-row layout  [b,h,s, perm8(d)]  perm8(d) = (d&3)*16 + (d>>2)
// g_V: transposed packed           [b,h,d, 64*tile + perm8(s&63)]
__device__ float g_Q[B_*H_*S_*DK_];
__device__ float g_K[B_*H_*S_*DK_];
__device__ float g_V[B_*H_*S_*DK_];
__device__ float g_ctx[B_*S_*D_];     // [b,s,h*d]

__device__ __forceinline__ unsigned f2tf(float x) {
    unsigned r; asm("cvt.rna.tf32.f32 %0, %1;" : "=r"(r) : "f"(x)); return r;
}
__device__ __forceinline__ float f2tff(float x) { return __uint_as_float(f2tf(x)); }
__device__ __forceinline__ unsigned uf(float x) { return __float_as_uint(x); }

__device__ __forceinline__ void mma8(float* c, const unsigned* a, unsigned b0, unsigned b1) {
    asm volatile(
        "mma.sync.aligned.m16n8k8.row.col.f32.tf32.tf32.f32 "
        "{%0,%1,%2,%3}, {%4,%5,%6,%7}, {%8,%9}, {%0,%1,%2,%3};"
        : "+f"(c[0]), "+f"(c[1]), "+f"(c[2]), "+f"(c[3])
        : "r"(a[0]), "r"(a[1]), "r"(a[2]), "r"(a[3]), "r"(b0), "r"(b1));
}

// ---------------- GEMM core: 64x64 warp tiles (4 warps, 128 threads) ------
// Y[m,n] = (sum_k X[m,k]*W[n,k] + bias[n]) * scale
// CTA 128x128x32; warp grid 2x2; warp tile 64x64 (im 0..3 x jn 0..7).
// Fragment LDS per warp serves 128 MMAs (was 64 with 8 warps) -> ~20% fewer
// L1 wavefronts per k-tile. smem row: 32 k permuted pos=(k&3)*8+(k>>2), stride 36.
// modes: 0 plain [M,N]; 1 packed bhsd (Q/K); 2 transposed packed (V).
#define GK 1024
#define GN 1024

__device__ __forceinline__
void gemm_body(const float* __restrict__ X, const float* __restrict__ W,
               const float* __restrict__ bias, float scale,
               float* __restrict__ Y, int mode,
               float* Xs, float* Ws)
{
    const int tid  = threadIdx.x;
    const int lane = tid & 31;
    const int wid  = tid >> 5;
    const int g = lane >> 2, q = lane & 3;
    const int wm = wid >> 1, wn = wid & 1;          // 2 x 2 warp grid
    const int m0 = blockIdx.y * 128, n0 = blockIdx.x * 128;

    float c[4][8][4];
#pragma unroll
    for (int i = 0; i < 4; i++)
#pragma unroll
        for (int j = 0; j < 8; j++)
#pragma unroll
            for (int k = 0; k < 4; k++) c[i][j][k] = 0.0f;

    for (int k0 = 0; k0 < GK; k0 += 32) {
#pragma unroll
        for (int i = 0; i < 8; i++) {
            int idx = tid + i * 128;            // 0..1023
            int row = idx >> 3;                 // 0..127
            int kq  = (idx & 7) * 4;            // 0..28
            int base = row * 36 + (kq >> 2);
            float4 xv = *(const float4*)(X + (size_t)(m0 + row) * GK + k0 + kq);
            Xs[base     ] = f2tff(xv.x);
            Xs[base +  8] = f2tff(xv.y);
            Xs[base + 16] = f2tff(xv.z);
            Xs[base + 24] = f2tff(xv.w);
            float4 wv = *(const float4*)(W + (size_t)(n0 + row) * GK + k0 + kq);
            Ws[base     ] = f2tff(wv.x);
            Ws[base +  8] = f2tff(wv.y);
            Ws[base + 16] = f2tff(wv.z);
            Ws[base + 24] = f2tff(wv.w);
        }
        __syncthreads();

#pragma unroll
        for (int p = 0; p < 2; p++) {
            const int cofs = q * 8 + 4 * p;
            unsigned bb[8][4];
#pragma unroll
            for (int jn = 0; jn < 8; jn++) {
                int nb = wn * 64 + jn * 8 + g;
                float4 wr = *(const float4*)(Ws + nb * 36 + cofs);
                bb[jn][0] = uf(wr.x); bb[jn][1] = uf(wr.y);
                bb[jn][2] = uf(wr.z); bb[jn][3] = uf(wr.w);
            }
#pragma unroll
            for (int im = 0; im < 4; im++) {
                int rb = wm * 64 + im * 16;
                float4 ar = *(const float4*)(Xs + (rb + g    ) * 36 + cofs);
                float4 br = *(const float4*)(Xs + (rb + g + 8) * 36 + cofs);
                unsigned aE[4] = { uf(ar.x), uf(br.x), uf(ar.y), uf(br.y) };
                unsigned aO[4] = { uf(ar.z), uf(br.z), uf(ar.w), uf(br.w) };
#pragma unroll
                for (int jn = 0; jn < 8; jn++) {
                    mma8(c[im][jn], aE, bb[jn][0], bb[jn][1]);
                    mma8(c[im][jn], aO, bb[jn][2], bb[jn][3]);
                }
            }
        }
        __syncthreads();
    }

    // epilogue
#pragma unroll
    for (int im = 0; im < 4; im++) {
#pragma unroll
        for (int jn = 0; jn < 8; jn++) {
            int n  = n0 + wn * 64 + jn * 8 + 2 * q;
            int mA = m0 + wm * 64 + im * 16 + g;
            int mB = mA + 8;
            float b0v = bias[n], b1v = bias[n + 1];
            float v0 = (c[im][jn][0] + b0v) * scale;
            float v1 = (c[im][jn][1] + b1v) * scale;
            float v2 = (c[im][jn][2] + b0v) * scale;
            float v3 = (c[im][jn][3] + b1v) * scale;
            if (mode == 0) {
                *(float2*)(Y + (size_t)mA * GN + n) = make_float2(v0, v1);
                *(float2*)(Y + (size_t)mB * GN + n) = make_float2(v2, v3);
            } else if (mode == 1) {
                int h = n >> 6, d0 = n & 63, d1 = d0 + 1;
                int p0 = (d0 & 3) * 16 + (d0 >> 2);
                int p1 = (d1 & 3) * 16 + (d1 >> 2);
                {
                    int b = mA >> 11, s = mA & (S_ - 1);
                    float* base = Y + (size_t)((b*H_ + h)*S_ + s) * 64;
                    base[p0] = f2tff(v0); base[p1] = f2tff(v1);
                }
                {
                    int b = mB >> 11, s = mB & (S_ - 1);
                    float* base = Y + (size_t)((b*H_ + h)*S_ + s) * 64;
                    base[p0] = f2tff(v2); base[p1] = f2tff(v3);
                }
            } else {
                int h = n >> 6, d0 = n & 63, d1 = d0 + 1;
                {
                    int b = mA >> 11, s = mA & (S_ - 1);
                    int ps = (s & ~63) + (s & 3) * 16 + ((s & 63) >> 2);
                    Y[(size_t)((b*H_ + h)*64 + d0) * S_ + ps] = f2tff(v0);
                    Y[(size_t)((b*H_ + h)*64 + d1) * S_ + ps] = f2tff(v1);
                }
                {
                    int b = mB >> 11, s = mB & (S_ - 1);
                    int ps = (s & ~63) + (s & 3) * 16 + ((s & 63) >> 2);
                    Y[(size_t)((b*H_ + h)*64 + d0) * S_ + ps] = f2tff(v2);
                    Y[(size_t)((b*H_ + h)*64 + d1) * S_ + ps] = f2tff(v3);
                }
            }
        }
    }
}

// Fused Q/K/V projection: blockIdx.z selects which projection this CTA does.
__global__ __launch_bounds__(128, 2)
void gemm_qkv(const float* __restrict__ query, const float* __restrict__ key,
              const float* __restrict__ value,
              const float* __restrict__ wq, const float* __restrict__ bq,
              const float* __restrict__ wk, const float* __restrict__ bk,
              const float* __restrict__ wv, const float* __restrict__ bv,
              float* __restrict__ gQ, float* __restrict__ gK, float* __restrict__ gV)
{
    __shared__ float Xs[128 * 36];
    __shared__ float Ws[128 * 36];
    const int z = blockIdx.z;
    if (z == 0)      gemm_body(query, wq, bq, 0.125f, gQ, 1, Xs, Ws);
    else if (z == 1) gemm_body(key,   wk, bk, 1.0f,   gK, 1, Xs, Ws);
    else             gemm_body(value, wv, bv, 1.0f,   gV, 2, Xs, Ws);
}

__global__ __launch_bounds__(128, 2)
void gemm_out(const float* __restrict__ X, const float* __restrict__ W,
              const float* __restrict__ bias, float* __restrict__ Y)
{
    __shared__ float Xs[128 * 36];
    __shared__ float Ws[128 * 36];
    gemm_body(X, W, bias, 1.0f, Y, 0, Xs, Ws);
}

// ---------------- flash attention (R12-exact: online max, raw fills) ------
// grid: (S/64, H, B); block 128 = 4 warps; warp owns 16 q-rows.
__global__ __launch_bounds__(128, 3)
void attn_tf32(const int* __restrict__ mask)
{
    __shared__ float Ks[64 * 64];
    __shared__ float Vs[64 * 64];
    __shared__ int   mks[64];

    const int tid  = threadIdx.x;
    const int lane = tid & 31;
    const int wid  = tid >> 5;
    const int g = lane >> 2, q = lane & 3;
    const int q0 = blockIdx.x * 64;
    const int h  = blockIdx.y;
    const int b  = blockIdx.z;
    const int wb = wid * 16;
    const int bh = b * H_ + h;
    const unsigned sw = (g & 1) << 2;

    // Q fragments direct from packed global (already tf32)
    const float* Qp = g_Q + (size_t)(bh * S_ + q0 + wb) * 64;
    unsigned qa[8][4];
#pragma unroll
    for (int p = 0; p < 4; p++) {
        float4 AR = *(const float4*)(Qp + (g    ) * 64 + (q * 4 + p) * 4);
        float4 BR = *(const float4*)(Qp + (g + 8) * 64 + (q * 4 + p) * 4);
        qa[2*p  ][0] = uf(AR.x); qa[2*p  ][1] = uf(BR.x);
        qa[2*p  ][2] = uf(AR.y); qa[2*p  ][3] = uf(BR.y);
        qa[2*p+1][0] = uf(AR.z); qa[2*p+1][1] = uf(BR.z);
        qa[2*p+1][2] = uf(AR.w); qa[2*p+1][3] = uf(BR.w);
    }
    const bool mr1 = mask[b*S_ + q0 + wb + g    ] != 0;
    const bool mr2 = mask[b*S_ + q0 + wb + g + 8] != 0;

    float m1 = -INFINITY, m2 = -INFINITY, l1 = 0.0f, l2 = 0.0f;
    float o[8][4];
#pragma unroll
    for (int j = 0; j < 8; j++)
#pragma unroll
        for (int k = 0; k < 4; k++) o[j][k] = 0.0f;

    const float4* K4 = (const float4*)(g_K + (size_t)bh * S_ * 64);
    const float*  Vt = g_V + (size_t)bh * 64 * S_;

    const int srcA = (lane & ~3) | (q >> 1);
    const int srcB = srcA + 2;
    const bool hi  = q & 1;

    for (int kt = 0; kt < S_ / 64; kt++) {
        __syncthreads();
#pragma unroll
        for (int t = 0; t < 8; t++) {
            int id  = tid + t * 128;
            int row = id >> 4, c16 = id & 15;
            int ph  = (c16 ^ ((row & 1) << 2)) << 2;
            *(float4*)(Ks + row * 64 + ph) = K4[(size_t)(kt * 64 + row) * 16 + c16];
            *(float4*)(Vs + row * 64 + ph) =
                *(const float4*)(Vt + (size_t)row * S_ + kt * 64 + c16 * 4);
        }
        if (tid < 64) mks[tid] = mask[b*S_ + kt*64 + tid];
        __syncthreads();

        // S = Q @ K^T
        float s[8][4];
#pragma unroll
        for (int j = 0; j < 8; j++) {
            s[j][0] = s[j][1] = s[j][2] = s[j][3] = 0.0f;
            const float* Kr = Ks + (j * 8 + g) * 64;
#pragma unroll
            for (int t = 0; t < 4; t++) {
                int kkp = (t + q) & 3;
                float4 w = *(const float4*)(Kr + (((q * 4 + kkp) ^ sw) << 2));
                mma8(s[j], qa[2*kkp  ], uf(w.x), uf(w.y));
                mma8(s[j], qa[2*kkp+1], uf(w.z), uf(w.w));
            }
        }

        // mask
#pragma unroll
        for (int j = 0; j < 8; j++) {
            int c0 = j * 8 + 2 * q;
            bool k0m = mks[c0] != 0, k1m = mks[c0 + 1] != 0;
            s[j][0] = (mr1 && k0m) ? s[j][0] : NEGV;
            s[j][1] = (mr1 && k1m) ? s[j][1] : NEGV;
            s[j][2] = (mr2 && k0m) ? s[j][2] : NEGV;
            s[j][3] = (mr2 && k1m) ? s[j][3] : NEGV;
        }

        // online softmax
        float t1 = -INFINITY, t2 = -INFINITY;
#pragma unroll
        for (int j = 0; j < 8; j++) {
            t1 = fmaxf(t1, fmaxf(s[j][0], s[j][1]));
            t2 = fmaxf(t2, fmaxf(s[j][2], s[j][3]));
        }
        t1 = fmaxf(t1, __shfl_xor_sync(0xffffffffu, t1, 1));
        t1 = fmaxf(t1, __shfl_xor_sync(0xffffffffu, t1, 2));
        t2 = fmaxf(t2, __shfl_xor_sync(0xffffffffu, t2, 1));
        t2 = fmaxf(t2, __shfl_xor_sync(0xffffffffu, t2, 2));

        float n1 = fmaxf(m1, t1), n2 = fmaxf(m2, t2);
        float a1 = __expf(m1 - n1), a2 = __expf(m2 - n2);
        m1 = n1; m2 = n2;

        float r1 = 0.0f, r2 = 0.0f;
#pragma unroll
        for (int j = 0; j < 8; j++) {
            s[j][0] = __expf(s[j][0] - n1); s[j][1] = __expf(s[j][1] - n1);
            s[j][2] = __expf(s[j][2] - n2); s[j][3] = __expf(s[j][3] - n2);
            r1 += s[j][0] + s[j][1];
            r2 += s[j][2] + s[j][3];
        }
        r1 += __shfl_xor_sync(0xffffffffu, r1, 1);
        r1 += __shfl_xor_sync(0xffffffffu, r1, 2);
        r2 += __shfl_xor_sync(0xffffffffu, r2, 1);
        r2 += __shfl_xor_sync(0xffffffffu, r2, 2);
        l1 = l1 * a1 + r1;
        l2 = l2 * a2 + r2;
#pragma unroll
        for (int j = 0; j < 8; j++) {
            o[j][0] *= a1; o[j][1] *= a1; o[j][2] *= a2; o[j][3] *= a2;
        }

        // P: C-layout -> A-fragment via shuffles
        unsigned pa[8][4];
#pragma unroll
        for (int kk = 0; kk < 8; kk++) {
            float u0 = __shfl_sync(0xffffffffu, s[kk][0], srcA);
            float u1 = __shfl_sync(0xffffffffu, s[kk][1], srcA);
            float u2 = __shfl_sync(0xffffffffu, s[kk][2], srcA);
            float u3 = __shfl_sync(0xffffffffu, s[kk][3], srcA);
            float v0 = __shfl_sync(0xffffffffu, s[kk][0], srcB);
            float v1 = __shfl_sync(0xffffffffu, s[kk][1], srcB);
            float v2 = __shfl_sync(0xffffffffu, s[kk][2], srcB);
            float v3 = __shfl_sync(0xffffffffu, s[kk][3], srcB);
            pa[kk][0] = f2tf(hi ? u1 : u0);
            pa[kk][1] = f2tf(hi ? u3 : u2);
            pa[kk][2] = f2tf(hi ? v1 : v0);
            pa[kk][3] = f2tf(hi ? v3 : v2);
        }

        // O += P @ V
#pragma unroll
        for (int j = 0; j < 8; j++) {
            const float* Vr = Vs + (j * 8 + g) * 64;
#pragma unroll
            for (int t = 0; t < 4; t++) {
                int kkp = (t + q) & 3;
                float4 w = *(const float4*)(Vr + (((q * 4 + kkp) ^ sw) << 2));
                mma8(o[j], pa[2*kkp  ], uf(w.x), uf(w.y));
                mma8(o[j], pa[2*kkp+1], uf(w.z), uf(w.w));
            }
        }
    }

    // epilogue
    float i1 = 1.0f / l1, i2 = 1.0f / l2;
    int r1g = q0 + wb + g, r2g = r1g + 8;
#pragma unroll
    for (int j = 0; j < 8; j++) {
        int col = h * 64 + j * 8 + 2 * q;
        *(float2*)(g_ctx + (size_t)(b*S_ + r1g) * D_ + col) =
            make_float2(o[j][0]*i1, o[j][1]*i1);
        *(float2*)(g_ctx + (size_t)(b*S_ + r2g) * D_ + col) =
            make_float2(o[j][2]*i2, o[j][3]*i2);
    }
}

// ---------------- host ----------------
extern "C" void kernel_launch(void* const* d_in, const int* in_sizes, int n_in,
                              void* d_out, int out_size)
{
    const float* query = (const float*)d_in[0];
    const float* key   = (const float*)d_in[1];
    const float* value = (const float*)d_in[2];
    const int*   mask  = (const int*)  d_in[3];
    const float* wq = (const float*)d_in[4];
    const float* bq = (const float*)d_in[5];
    const float* wk = (const float*)d_in[6];
    const float* bk = (const float*)d_in[7];
    const float* wv = (const float*)d_in[8];
    const float* bv = (const float*)d_in[9];
    const float* wo = (const float*)d_in[10];
    const float* bo = (const float*)d_in[11];

    float *gQ, *gK, *gV, *gctx;
    cudaGetSymbolAddress((void**)&gQ,   g_Q);
    cudaGetSymbolAddress((void**)&gK,   g_K);
    cudaGetSymbolAddress((void**)&gV,   g_V);
    cudaGetSymbolAddress((void**)&gctx, g_ctx);

    dim3 gq(GN / 128, 4096 / 128, 3);   // (8, 32, 3): fused Q/K/V projections
    gemm_qkv<<<gq, 128>>>(query, key, value, wq, bq, wk, bk, wv, bv, gQ, gK, gV);

    attn_tf32<<<dim3(S_/64, H_, B_), 128>>>(mask);

    dim3 go(GN / 128, 4096 / 128);      // (8, 32)
    gemm_out<<<go, 128>>>(gctx, wo, bo, (float*)d_out);
}